// round 8
// baseline (speedup 1.0000x reference)
#include <cuda_runtime.h>

// SparseDownSample: 2x2 max-pool keyed on depth (first-max tie-break),
// gather winning position from depth (1ch) and geo (16ch).
// depth: [B,1,H,W] f32, geo: [B,C,H,W] f32
// out  : depth_fold [B,1,H/2,W/2] followed by geo_fold [B,C,H/2,W/2]
//
// R8: R3's winning shape (CB=8 staged, lane-dense float4, ldcs/stcs) made
// persistent: 444 blocks (148 SM x 3 resident) with grid-stride loop to
// eliminate the partial tail wave.

constexpr int B  = 8;
constexpr int C  = 16;
constexpr int H  = 352;
constexpr int W  = 1216;
constexpr int H2 = H / 2;    // 176
constexpr int W2 = W / 2;    // 608
constexpr int WP = W2 / 2;   // 304 output-pixel PAIRS per row
constexpr int DEPTH_OUT_ELEMS = B * H2 * W2;  // 856064
constexpr int CB = 8;        // channels per load batch (16 float4 = 64 regs live)
constexpr int TOTAL = B * H2 * WP;  // 428032 work items

__global__ __launch_bounds__(256)
void sds_kernel(const float* __restrict__ depth,
                const float* __restrict__ geo,
                float* __restrict__ out)
{
    const int stride = gridDim.x * blockDim.x;

    for (int t = blockIdx.x * blockDim.x + threadIdx.x; t < TOTAL; t += stride) {
        const int xp   = t % WP;         // which float4 within the row
        const int rest = t / WP;
        const int y    = rest % H2;
        const int b    = rest / H2;

        // ---- depth: two rows, one float4 each (covers 2 output pixels) ----
        const float* drow = depth + (size_t)(b * H + 2 * y) * W;
        const float4 d0 = __ldcs(reinterpret_cast<const float4*>(drow)     + xp);
        const float4 d1 = __ldcs(reinterpret_cast<const float4*>(drow + W) + xp);

        // argmax, first-max wins (strict > keeps lowest index), order:
        // 0=(r0,c0) 1=(r0,c1) 2=(r1,c0) 3=(r1,c1) -- matches unfold kh,kw order
        int   i0 = 0; float v0 = d0.x;
        if (d0.y > v0) { v0 = d0.y; i0 = 1; }
        if (d1.x > v0) { v0 = d1.x; i0 = 2; }
        if (d1.y > v0) { v0 = d1.y; i0 = 3; }

        int   i1 = 0; float v1 = d0.z;
        if (d0.w > v1) { v1 = d0.w; i1 = 1; }
        if (d1.z > v1) { v1 = d1.z; i1 = 2; }
        if (d1.w > v1) { v1 = d1.w; i1 = 3; }

        const size_t dpix = (size_t)(b * H2 + y) * W2 + (size_t)xp * 2;
        __stcs(reinterpret_cast<float2*>(out) + dpix / 2, make_float2(v0, v1));

        // ---- geo: 16 channels in batches of CB; stage loads, then select ----
        float* gout = out + DEPTH_OUT_ELEMS;
        const float* grow = geo + ((size_t)b * C * H + 2 * y) * W;
        const size_t obase = ((size_t)(b * C) * H2 + y) * W2 + (size_t)xp * 2;

        #pragma unroll
        for (int cb = 0; cb < C; cb += CB) {
            float4 g0[CB], g1[CB];
            // phase 1: issue all loads back-to-back (front-batched 2*CB LDG.128)
            #pragma unroll
            for (int j = 0; j < CB; ++j) {
                const float* r0 = grow + (size_t)(cb + j) * (H * W);
                g0[j] = __ldcs(reinterpret_cast<const float4*>(r0)     + xp);
                g1[j] = __ldcs(reinterpret_cast<const float4*>(r0 + W) + xp);
            }
            // phase 2: select + store
            #pragma unroll
            for (int j = 0; j < CB; ++j) {
                const float s0 = (i0 == 0) ? g0[j].x : (i0 == 1) ? g0[j].y
                               : (i0 == 2) ? g1[j].x : g1[j].y;
                const float s1 = (i1 == 0) ? g0[j].z : (i1 == 1) ? g0[j].w
                               : (i1 == 2) ? g1[j].z : g1[j].w;
                const size_t o = obase + (size_t)(cb + j) * (H2 * W2);
                __stcs(reinterpret_cast<float2*>(gout) + o / 2, make_float2(s0, s1));
            }
        }
    }
}

extern "C" void kernel_launch(void* const* d_in, const int* in_sizes, int n_in,
                              void* d_out, int out_size)
{
    const float* depth = (const float*)d_in[0];
    const float* geo   = (const float*)d_in[1];
    float* out = (float*)d_out;

    const int threads = 256;
    const int blocks  = 444;   // 148 SMs x 3 resident CTAs @ ~78 regs
    sds_kernel<<<blocks, threads>>>(depth, geo, out);
}

// round 10
// speedup vs baseline: 1.1420x; 1.1420x over previous
#include <cuda_runtime.h>

// SparseDownSample: 2x2 max-pool keyed on depth (first-max tie-break),
// gather winning position from depth (1ch) and geo (16ch).
// depth: [B,1,H,W] f32, geo: [B,C,H,W] f32
// out  : depth_fold [B,1,H/2,W/2] followed by geo_fold [B,C,H/2,W/2]
//
// R10 == R3 exactly (best measured: 40.4us kernel / 43.0us bench).
// Reproducibility control; R9 submission of the same source hit an infra
// failure before measuring.

constexpr int B  = 8;
constexpr int C  = 16;
constexpr int H  = 352;
constexpr int W  = 1216;
constexpr int H2 = H / 2;    // 176
constexpr int W2 = W / 2;    // 608
constexpr int WP = W2 / 2;   // 304 output-pixel PAIRS per row (one float4 of input per row)
constexpr int DEPTH_OUT_ELEMS = B * H2 * W2;  // 856064
constexpr int CB = 8;        // channels per load batch (16 float4 = 64 regs live)

__global__ __launch_bounds__(256)
void sds_kernel(const float* __restrict__ depth,
                const float* __restrict__ geo,
                float* __restrict__ out)
{
    const int t = blockIdx.x * blockDim.x + threadIdx.x;
    const int total = B * H2 * WP;   // 428032
    if (t >= total) return;

    const int xp   = t % WP;         // which float4 within the row
    const int rest = t / WP;
    const int y    = rest % H2;
    const int b    = rest / H2;

    // ---- depth: two rows, one float4 each (covers 2 output pixels) ----
    const float* drow = depth + (size_t)(b * H + 2 * y) * W;
    const float4 d0 = __ldg(reinterpret_cast<const float4*>(drow) + xp);
    const float4 d1 = __ldg(reinterpret_cast<const float4*>(drow + W) + xp);

    // argmax, first-max wins (strict > keeps lowest index), order:
    // 0=(r0,c0) 1=(r0,c1) 2=(r1,c0) 3=(r1,c1)  -- matches unfold kh,kw ordering
    int   i0 = 0; float v0 = d0.x;
    if (d0.y > v0) { v0 = d0.y; i0 = 1; }
    if (d1.x > v0) { v0 = d1.x; i0 = 2; }
    if (d1.y > v0) { v0 = d1.y; i0 = 3; }

    int   i1 = 0; float v1 = d0.z;
    if (d0.w > v1) { v1 = d0.w; i1 = 1; }
    if (d1.z > v1) { v1 = d1.z; i1 = 2; }
    if (d1.w > v1) { v1 = d1.w; i1 = 3; }

    // depth_fold store (float2, 8B aligned: xp*2 is even)
    const size_t dpix = (size_t)(b * H2 + y) * W2 + (size_t)xp * 2;
    __stcs(reinterpret_cast<float2*>(out) + dpix / 2, make_float2(v0, v1));

    // ---- geo: 16 channels in batches of CB; stage loads, then select ----
    float* gout = out + DEPTH_OUT_ELEMS;
    const float* grow = geo + ((size_t)b * C * H + 2 * y) * W;   // channel 0, row 2y
    const size_t obase = ((size_t)(b * C) * H2 + y) * W2 + (size_t)xp * 2;

    #pragma unroll
    for (int cb = 0; cb < C; cb += CB) {
        float4 g0[CB], g1[CB];
        // phase 1: issue all loads back-to-back (front-batched LDG.128, MLP=2*CB)
        #pragma unroll
        for (int j = 0; j < CB; ++j) {
            const float* r0 = grow + (size_t)(cb + j) * (H * W);
            g0[j] = __ldcs(reinterpret_cast<const float4*>(r0) + xp);
            g1[j] = __ldcs(reinterpret_cast<const float4*>(r0 + W) + xp);
        }
        // phase 2: select + store
        #pragma unroll
        for (int j = 0; j < CB; ++j) {
            const float s0 = (i0 == 0) ? g0[j].x : (i0 == 1) ? g0[j].y
                           : (i0 == 2) ? g1[j].x : g1[j].y;
            const float s1 = (i1 == 0) ? g0[j].z : (i1 == 1) ? g0[j].w
                           : (i1 == 2) ? g1[j].z : g1[j].w;
            const size_t o = obase + (size_t)(cb + j) * (H2 * W2);
            __stcs(reinterpret_cast<float2*>(gout) + o / 2, make_float2(s0, s1));
        }
    }
}

extern "C" void kernel_launch(void* const* d_in, const int* in_sizes, int n_in,
                              void* d_out, int out_size)
{
    const float* depth = (const float*)d_in[0];
    const float* geo   = (const float*)d_in[1];
    float* out = (float*)d_out;

    const int total   = B * H2 * WP;          // 428032 threads
    const int threads = 256;
    const int blocks  = (total + threads - 1) / threads;
    sds_kernel<<<blocks, threads>>>(depth, geo, out);
}

// round 11
// speedup vs baseline: 1.1698x; 1.0244x over previous
#include <cuda_runtime.h>

// SparseDownSample: 2x2 max-pool keyed on depth (first-max tie-break),
// gather winning position from depth (1ch) and geo (16ch).
// depth: [B,1,H,W] f32, geo: [B,C,H,W] f32
// out  : depth_fold [B,1,H/2,W/2] followed by geo_fold [B,C,H/2,W/2]
//
// R11 = champion (R3/R10: CB=8, 256thr, ldcs geo / stcs stores) with the
// opening load burst made explicit: depth(2) + geo batch-0(16) LDG.128 all
// issued before the argmax consumes depth. Peak live regs ~84 (3 CTAs/SM).

constexpr int B  = 8;
constexpr int C  = 16;
constexpr int H  = 352;
constexpr int W  = 1216;
constexpr int H2 = H / 2;    // 176
constexpr int W2 = W / 2;    // 608
constexpr int WP = W2 / 2;   // 304 output-pixel PAIRS per row
constexpr int DEPTH_OUT_ELEMS = B * H2 * W2;  // 856064
constexpr int CB = 8;        // channels per load batch (16 float4 live)

__global__ __launch_bounds__(256)
void sds_kernel(const float* __restrict__ depth,
                const float* __restrict__ geo,
                float* __restrict__ out)
{
    const int t = blockIdx.x * blockDim.x + threadIdx.x;
    const int total = B * H2 * WP;   // 428032
    if (t >= total) return;

    const int xp   = t % WP;         // which float4 within the row
    const int rest = t / WP;
    const int y    = rest % H2;
    const int b    = rest / H2;

    // ============ opening burst: depth (2) + geo batch 0 (16) ============
    const float* drow = depth + (size_t)(b * H + 2 * y) * W;
    const float4 d0 = __ldg(reinterpret_cast<const float4*>(drow) + xp);
    const float4 d1 = __ldg(reinterpret_cast<const float4*>(drow + W) + xp);

    const float* grow = geo + ((size_t)b * C * H + 2 * y) * W;   // ch 0, row 2y
    float4 g0[CB], g1[CB];
    #pragma unroll
    for (int j = 0; j < CB; ++j) {
        const float* r0 = grow + (size_t)j * (H * W);
        g0[j] = __ldcs(reinterpret_cast<const float4*>(r0) + xp);
        g1[j] = __ldcs(reinterpret_cast<const float4*>(r0 + W) + xp);
    }

    // ---- argmax, first-max wins (strict > keeps lowest index), order:
    // 0=(r0,c0) 1=(r0,c1) 2=(r1,c0) 3=(r1,c1) -- matches unfold kh,kw order
    int   i0 = 0; float v0 = d0.x;
    if (d0.y > v0) { v0 = d0.y; i0 = 1; }
    if (d1.x > v0) { v0 = d1.x; i0 = 2; }
    if (d1.y > v0) { v0 = d1.y; i0 = 3; }

    int   i1 = 0; float v1 = d0.z;
    if (d0.w > v1) { v1 = d0.w; i1 = 1; }
    if (d1.z > v1) { v1 = d1.z; i1 = 2; }
    if (d1.w > v1) { v1 = d1.w; i1 = 3; }

    const size_t dpix = (size_t)(b * H2 + y) * W2 + (size_t)xp * 2;
    __stcs(reinterpret_cast<float2*>(out) + dpix / 2, make_float2(v0, v1));

    float* gout = out + DEPTH_OUT_ELEMS;
    const size_t obase = ((size_t)(b * C) * H2 + y) * W2 + (size_t)xp * 2;

    // ---- select + store batch 0 ----
    #pragma unroll
    for (int j = 0; j < CB; ++j) {
        const float s0 = (i0 == 0) ? g0[j].x : (i0 == 1) ? g0[j].y
                       : (i0 == 2) ? g1[j].x : g1[j].y;
        const float s1 = (i1 == 0) ? g0[j].z : (i1 == 1) ? g0[j].w
                       : (i1 == 2) ? g1[j].z : g1[j].w;
        const size_t o = obase + (size_t)j * (H2 * W2);
        __stcs(reinterpret_cast<float2*>(gout) + o / 2, make_float2(s0, s1));
    }

    // ---- batch 1: load burst, then select + store ----
    #pragma unroll
    for (int j = 0; j < CB; ++j) {
        const float* r0 = grow + (size_t)(CB + j) * (H * W);
        g0[j] = __ldcs(reinterpret_cast<const float4*>(r0) + xp);
        g1[j] = __ldcs(reinterpret_cast<const float4*>(r0 + W) + xp);
    }
    #pragma unroll
    for (int j = 0; j < CB; ++j) {
        const float s0 = (i0 == 0) ? g0[j].x : (i0 == 1) ? g0[j].y
                       : (i0 == 2) ? g1[j].x : g1[j].y;
        const float s1 = (i1 == 0) ? g0[j].z : (i1 == 1) ? g0[j].w
                       : (i1 == 2) ? g1[j].z : g1[j].w;
        const size_t o = obase + (size_t)(CB + j) * (H2 * W2);
        __stcs(reinterpret_cast<float2*>(gout) + o / 2, make_float2(s0, s1));
    }
}

extern "C" void kernel_launch(void* const* d_in, const int* in_sizes, int n_in,
                              void* d_out, int out_size)
{
    const float* depth = (const float*)d_in[0];
    const float* geo   = (const float*)d_in[1];
    float* out = (float*)d_out;

    const int total   = B * H2 * WP;          // 428032 threads
    const int threads = 256;
    const int blocks  = (total + threads - 1) / threads;
    sds_kernel<<<blocks, threads>>>(depth, geo, out);
}

// round 12
// speedup vs baseline: 1.1898x; 1.0170x over previous
#include <cuda_runtime.h>

// SparseDownSample: 2x2 max-pool keyed on depth (first-max tie-break),
// gather winning position from depth (1ch) and geo (16ch).
// depth: [B,1,H,W] f32, geo: [B,C,H,W] f32
// out  : depth_fold [B,1,H/2,W/2] followed by geo_fold [B,C,H/2,W/2]
//
// FINAL (champion, reproduced 3x at 40.2us kernel): 2 output px/thread,
// lane-dense float4 loads, CB=8 staged load batches (16 front-batched
// LDG.128), evict-first streaming hints on geo loads + all stores.
// At ~6.1 TB/s achieved mixed R/W DRAM bandwidth this sits on the byte-
// traffic roofline (233 MB reads + 58 MB writes ~= 40us floor).

constexpr int B  = 8;
constexpr int C  = 16;
constexpr int H  = 352;
constexpr int W  = 1216;
constexpr int H2 = H / 2;    // 176
constexpr int W2 = W / 2;    // 608
constexpr int WP = W2 / 2;   // 304 output-pixel PAIRS per row
constexpr int DEPTH_OUT_ELEMS = B * H2 * W2;  // 856064
constexpr int CB = 8;        // channels per load batch (16 float4 live)

__global__ __launch_bounds__(256)
void sds_kernel(const float* __restrict__ depth,
                const float* __restrict__ geo,
                float* __restrict__ out)
{
    const int t = blockIdx.x * blockDim.x + threadIdx.x;
    const int total = B * H2 * WP;   // 428032
    if (t >= total) return;

    const int xp   = t % WP;         // which float4 within the row
    const int rest = t / WP;
    const int y    = rest % H2;
    const int b    = rest / H2;

    // ============ opening burst: depth (2) + geo batch 0 (16) ============
    const float* drow = depth + (size_t)(b * H + 2 * y) * W;
    const float4 d0 = __ldg(reinterpret_cast<const float4*>(drow) + xp);
    const float4 d1 = __ldg(reinterpret_cast<const float4*>(drow + W) + xp);

    const float* grow = geo + ((size_t)b * C * H + 2 * y) * W;   // ch 0, row 2y
    float4 g0[CB], g1[CB];
    #pragma unroll
    for (int j = 0; j < CB; ++j) {
        const float* r0 = grow + (size_t)j * (H * W);
        g0[j] = __ldcs(reinterpret_cast<const float4*>(r0) + xp);
        g1[j] = __ldcs(reinterpret_cast<const float4*>(r0 + W) + xp);
    }

    // ---- argmax, first-max wins (strict > keeps lowest index), order:
    // 0=(r0,c0) 1=(r0,c1) 2=(r1,c0) 3=(r1,c1) -- matches unfold kh,kw order
    int   i0 = 0; float v0 = d0.x;
    if (d0.y > v0) { v0 = d0.y; i0 = 1; }
    if (d1.x > v0) { v0 = d1.x; i0 = 2; }
    if (d1.y > v0) { v0 = d1.y; i0 = 3; }

    int   i1 = 0; float v1 = d0.z;
    if (d0.w > v1) { v1 = d0.w; i1 = 1; }
    if (d1.z > v1) { v1 = d1.z; i1 = 2; }
    if (d1.w > v1) { v1 = d1.w; i1 = 3; }

    const size_t dpix = (size_t)(b * H2 + y) * W2 + (size_t)xp * 2;
    __stcs(reinterpret_cast<float2*>(out) + dpix / 2, make_float2(v0, v1));

    float* gout = out + DEPTH_OUT_ELEMS;
    const size_t obase = ((size_t)(b * C) * H2 + y) * W2 + (size_t)xp * 2;

    // ---- select + store batch 0 ----
    #pragma unroll
    for (int j = 0; j < CB; ++j) {
        const float s0 = (i0 == 0) ? g0[j].x : (i0 == 1) ? g0[j].y
                       : (i0 == 2) ? g1[j].x : g1[j].y;
        const float s1 = (i1 == 0) ? g0[j].z : (i1 == 1) ? g0[j].w
                       : (i1 == 2) ? g1[j].z : g1[j].w;
        const size_t o = obase + (size_t)j * (H2 * W2);
        __stcs(reinterpret_cast<float2*>(gout) + o / 2, make_float2(s0, s1));
    }

    // ---- batch 1: load burst, then select + store ----
    #pragma unroll
    for (int j = 0; j < CB; ++j) {
        const float* r0 = grow + (size_t)(CB + j) * (H * W);
        g0[j] = __ldcs(reinterpret_cast<const float4*>(r0) + xp);
        g1[j] = __ldcs(reinterpret_cast<const float4*>(r0 + W) + xp);
    }
    #pragma unroll
    for (int j = 0; j < CB; ++j) {
        const float s0 = (i0 == 0) ? g0[j].x : (i0 == 1) ? g0[j].y
                       : (i0 == 2) ? g1[j].x : g1[j].y;
        const float s1 = (i1 == 0) ? g0[j].z : (i1 == 1) ? g0[j].w
                       : (i1 == 2) ? g1[j].z : g1[j].w;
        const size_t o = obase + (size_t)(CB + j) * (H2 * W2);
        __stcs(reinterpret_cast<float2*>(gout) + o / 2, make_float2(s0, s1));
    }
}

extern "C" void kernel_launch(void* const* d_in, const int* in_sizes, int n_in,
                              void* d_out, int out_size)
{
    const float* depth = (const float*)d_in[0];
    const float* geo   = (const float*)d_in[1];
    float* out = (float*)d_out;

    const int total   = B * H2 * WP;          // 428032 threads
    const int threads = 256;
    const int blocks  = (total + threads - 1) / threads;
    sds_kernel<<<blocks, threads>>>(depth, geo, out);
}